// round 5
// baseline (speedup 1.0000x reference)
#include <cuda_runtime.h>
#include <cuda_bf16.h>

// BiLSTM: B=128, S=1024, D=128, H=256, fp32.
// Phase 1: zx[dir][col][t*128+b] = bias[col] + sum_{k<128} W[dir][g,h,k]*x[k*131072 + t*128 + b]
// Phase 2: persistent recurrent kernel, 64 CTAs/direction, 256 thr (8 warps: 1 unit/warp,
//          2 batches/lane), flag barrier per step (spin only on same-batch-half producers).
// All GEMM math uses packed fma.rn.f32x2 (FFMA2: 2 fp32 MACs/lane/instr on sm_103a).

#define S_LEN 1024
#define NTB   131072                      // S*B
#define ZX_DIR ((size_t)1024 * (size_t)NTB)

typedef unsigned long long ull;

__device__ float g_zx[2ull * 1024ull * NTB];   // 1 GB scratch
__device__ float g_h[2][2][256 * 128];         // [dir][buf][hid][b]
__device__ int   g_flags[2][64];

// ---------------- f32x2 helpers ----------------
__device__ __forceinline__ ull dup2(float x) {
    ull r; asm("mov.b64 %0, {%1, %1};" : "=l"(r) : "f"(x)); return r;
}
__device__ __forceinline__ void unpack2(ull v, float& lo, float& hi) {
    asm("mov.b64 {%0, %1}, %2;" : "=f"(lo), "=f"(hi) : "l"(v));
}
__device__ __forceinline__ void fma2(ull& acc, ull a, ull b) {
    asm("fma.rn.f32x2 %0, %1, %2, %0;" : "+l"(acc) : "l"(a), "l"(b));
}

// ---------------- cp.async (L2 path, bypasses L1) ----------------
__device__ __forceinline__ void cp_async16(void* dst, const void* src) {
    unsigned d = (unsigned)__cvta_generic_to_shared(dst);
    asm volatile("cp.async.cg.shared.global [%0], [%1], 16;" :: "r"(d), "l"(src) : "memory");
}
__device__ __forceinline__ void cp_commit() {
    asm volatile("cp.async.commit_group;" ::: "memory");
}
template<int N> __device__ __forceinline__ void cp_wait() {
    asm volatile("cp.async.wait_group %0;" :: "n"(N) : "memory");
}

__device__ __forceinline__ float sigf(float x) {
    float e = __expf(-x);
    return __fdividef(1.0f, 1.0f + e);
}
__device__ __forceinline__ float tanh_acc(float x) {
    float ax = fabsf(x);
    float e = __expf(-2.0f * ax);
    float t = __fdividef(1.0f - e, 1.0f + e);
    return copysignf(t, x);
}

// ---------------- init ----------------
__global__ void zero_flags_kernel() {
    ((int*)g_flags)[threadIdx.x] = 0;
}

// ---------------- Phase 1: input GEMM ----------------
// grid (8 colTiles, 1024 nTiles, 2 dirs), 256 threads, dyn smem 133120 B
__global__ void __launch_bounds__(256, 1)
zx_gemm_kernel(const float* __restrict__ xin,
               const float* __restrict__ Wf, const float* __restrict__ bf,
               const float* __restrict__ Wb, const float* __restrict__ bb)
{
    extern __shared__ float zsm[];
    float* Asm = zsm;               // [k 0..127][col 0..127], pitch 132
    float* Bsm = zsm + 128 * 132;   // [k 0..127][n 0..127], pitch 128

    const int dir = blockIdx.z;
    const float* W    = dir ? Wb : Wf;
    const float* bias = dir ? bb : bf;
    const int ct = blockIdx.x;      // col tile (128 cols each)
    const int nt = blockIdx.y;      // (t,b) tile of 128
    const int tid = threadIdx.x;

    // A tile: W input part (k<128), transposed into Asm[k][c]
    {
        int c  = tid >> 1;
        int kh = (tid & 1) * 64;
        int colg = ct * 128 + c;
        int g = colg >> 8, h = colg & 255;
        const float* srcA = W + g * 98304 + h * 384 + kh;
        #pragma unroll
        for (int i = 0; i < 64; i += 4) {
            float4 v = *(const float4*)(srcA + i);
            Asm[(kh + i + 0) * 132 + c] = v.x;
            Asm[(kh + i + 1) * 132 + c] = v.y;
            Asm[(kh + i + 2) * 132 + c] = v.z;
            Asm[(kh + i + 3) * 132 + c] = v.w;
        }
    }
    // B tile: Bsm[k][n] = x[k*131072 + nt*128 + n]
    {
        int r  = tid >> 1;
        int nh = (tid & 1) * 64;
        const float* srcB = xin + (size_t)r * NTB + (size_t)nt * 128 + nh;
        #pragma unroll
        for (int i = 0; i < 64; i += 4)
            *(float4*)&Bsm[r * 128 + nh + i] = *(const float4*)(srcB + i);
    }
    __syncthreads();

    const int tn = tid & 15;        // n group of 8
    const int tc = tid >> 4;        // col group of 8
    const int colt = ct * 128 + tc * 8;

    ull acc[8][4];
    #pragma unroll
    for (int c = 0; c < 8; ++c) {
        ull bd = dup2(bias[colt + c]);
        acc[c][0] = bd; acc[c][1] = bd; acc[c][2] = bd; acc[c][3] = bd;
    }

    #pragma unroll 4
    for (int k = 0; k < 128; ++k) {
        const float* arow = &Asm[k * 132 + tc * 8];
        float4 a0 = *(const float4*)arow;
        float4 a1 = *(const float4*)(arow + 4);
        const longlong2* brow = (const longlong2*)&Bsm[k * 128 + tn * 8];
        longlong2 bA = brow[0], bB = brow[1];
        ull bp0 = (ull)bA.x, bp1 = (ull)bA.y, bp2 = (ull)bB.x, bp3 = (ull)bB.y;
#define ROWF(c, av) { ull ad = dup2(av); \
        fma2(acc[c][0], ad, bp0); fma2(acc[c][1], ad, bp1); \
        fma2(acc[c][2], ad, bp2); fma2(acc[c][3], ad, bp3); }
        ROWF(0, a0.x) ROWF(1, a0.y) ROWF(2, a0.z) ROWF(3, a0.w)
        ROWF(4, a1.x) ROWF(5, a1.y) ROWF(6, a1.z) ROWF(7, a1.w)
#undef ROWF
    }

    float* zd = g_zx + (size_t)dir * ZX_DIR;
    #pragma unroll
    for (int c = 0; c < 8; ++c) {
        size_t base = (size_t)(colt + c) * NTB + (size_t)nt * 128 + (size_t)tn * 8;
        longlong2 v0, v1;
        v0.x = (long long)acc[c][0]; v0.y = (long long)acc[c][1];
        v1.x = (long long)acc[c][2]; v1.y = (long long)acc[c][3];
        *(longlong2*)(zd + base)     = v0;
        *(longlong2*)(zd + base + 4) = v1;
    }
}

// ---------------- Phase 2: persistent recurrence ----------------
// warp w owns unit u0 = ug*8 + w; lane owns batches (bh*64 + lane*2, +1).
__device__ __forceinline__ void kblock(int K0, const float2* hsm2, const longlong2* wsmLL,
                                       int lane, int warp, ull afi[2], ull aco[2])
{
    #pragma unroll 8
    for (int k = K0; k < K0 + 64; ++k) {
        float2 h2 = hsm2[k * 32 + lane];
        longlong2 w0 = wsmLL[k * 8 + warp];     // {(f,i) pair, (c,o) pair} broadcast
        ull hd0 = dup2(h2.x), hd1 = dup2(h2.y);
        fma2(afi[0], hd0, (ull)w0.x); fma2(aco[0], hd0, (ull)w0.y);
        fma2(afi[1], hd1, (ull)w0.x); fma2(aco[1], hd1, (ull)w0.y);
    }
}

// grid 128 (64 CTAs/direction), 256 threads, dyn smem 122880 B (forces 1 CTA/SM)
__global__ void __launch_bounds__(256, 1)
lstm_seq_kernel(const float* __restrict__ Wf, const float* __restrict__ Wb,
                float* __restrict__ out)
{
    extern __shared__ float sm[];
    float* wsm = sm;                          // 8192 floats: [k][u(8)][g(4)]
    float* hsm = sm + 8192;                   // 16384 floats: [k][64 b]
    longlong2* wsmLL = (longlong2*)wsm;
    float2*    hsm2  = (float2*)hsm;
    float4*    hsm4  = (float4*)hsm;

    const int tid  = threadIdx.x;
    const int lane = tid & 31;
    const int warp = tid >> 5;                // 0..7
    const int blk  = blockIdx.x;
    const int dirq = blk >> 6;                // direction
    const int sub  = blk & 63;                // 0..63
    const int bh   = sub & 1;                 // batch half
    const int ug   = sub >> 1;                // unit group 0..31 -> units ug*8..+7
    const int u0   = ug * 8 + warp;           // this warp's hidden unit
    const int bbase = bh * 64 + lane * 2;     // this lane's first batch

    const float* W   = dirq ? Wb : Wf;
    float* hbuf0 = &g_h[dirq][0][0];
    float* hbuf1 = &g_h[dirq][1][0];
    int*   flags = g_flags[dirq];

    // load recurrent weights: wsm[k*32 + w*4 + g] = W[g][ug*8+w][128+k]
    for (int i = tid; i < 8192; i += 256) {
        int g = i & 3, w = (i >> 2) & 7, k = i >> 5;
        wsm[i] = W[g * 98304 + (ug * 8 + w) * 384 + 128 + k];
    }
    __syncthreads();

    // persistent zx pointers (one per gate), stepped by +-128 floats per step
    const int t0 = dirq ? (S_LEN - 1) : 0;
    const long long zstep = dirq ? -128LL : 128LL;
    const float* zp[4];
    {
        const float* zxd = g_zx + (size_t)dirq * ZX_DIR;
        const size_t nb0 = (size_t)t0 * 128 + bbase;
        #pragma unroll
        for (int g = 0; g < 4; ++g)
            zp[g] = zxd + (size_t)(g * 256 + u0) * (size_t)NTB + nb0;
    }

    float c[2] = {0.f, 0.f};
    float hn[2];

    for (int s = 0; s < S_LEN; ++s) {
        const int t = dirq ? (S_LEN - 1 - s) : s;

        // zx loads (stable data; issue before the spin to hide DRAM latency)
        float2 zf = *(const float2*)zp[0];
        float2 zi = *(const float2*)zp[1];
        float2 zc = *(const float2*)zp[2];
        float2 zo = *(const float2*)zp[3];
        #pragma unroll
        for (int p = 0; p < 4; ++p) zp[p] += zstep;

        ull afi[2] = {0ull, 0ull};
        ull aco[2] = {0ull, 0ull};

        if (s > 0) {
            // Our h-half (batches bh*64..+63) is produced only by the 32 CTAs
            // with the same batch-half parity: sub' = 2*i + bh. Spin on those.
            if (tid < 32) {
                const int* fp = &flags[tid * 2 + bh];
                int v;
                do {
                    asm volatile("ld.acquire.gpu.b32 %0, [%1];" : "=r"(v) : "l"(fp));
                } while (v < s);
            }
            __syncthreads();

            // stage h_prev (this CTA's 64-batch half) through L2, 4 chunks
            const float* hsrc = ((s & 1) ? hbuf0 : hbuf1) + bh * 64;
            #pragma unroll
            for (int ch = 0; ch < 4; ++ch) {
                int base = ch * 1024;
                #pragma unroll
                for (int i = 0; i < 4; ++i) {
                    int idx = base + tid + i * 256;
                    int k = idx >> 4, bg = idx & 15;
                    cp_async16(&hsm4[idx], hsrc + (size_t)k * 128 + bg * 4);
                }
                cp_commit();
            }
            cp_wait<3>(); __syncthreads(); kblock(0,   hsm2, wsmLL, lane, warp, afi, aco);
            cp_wait<2>(); __syncthreads(); kblock(64,  hsm2, wsmLL, lane, warp, afi, aco);
            cp_wait<1>(); __syncthreads(); kblock(128, hsm2, wsmLL, lane, warp, afi, aco);
            cp_wait<0>(); __syncthreads(); kblock(192, hsm2, wsmLL, lane, warp, afi, aco);
        }

        // epilogue: gates, cell, hidden (2 batches per thread)
        #pragma unroll
        for (int bb = 0; bb < 2; ++bb) {
            float af, ai, ac, ao;
            unpack2(afi[bb], af, ai);
            unpack2(aco[bb], ac, ao);
            float zF = (bb ? zf.y : zf.x) + af;
            float zI = (bb ? zi.y : zi.x) + ai;
            float zC = (bb ? zc.y : zc.x) + ac;
            float zO = (bb ? zo.y : zo.x) + ao;
            float fg = sigf(zF), ig = sigf(zI);
            float cg = tanh_acc(zC), og = sigf(zO);
            float cn = fg * c[bb] + ig * cg;
            c[bb] = cn;
            hn[bb] = og * tanh_acc(cn);
        }

        // publish h_next
        float* hwr = (s & 1) ? hbuf1 : hbuf0;
        *(float2*)(hwr + (size_t)u0 * 128 + bbase) = make_float2(hn[0], hn[1]);

        // main output: out[b][t][dir*256 + u]
        {
            size_t cix = (size_t)t * 512 + dirq * 256 + u0;
            out[(size_t)(bbase)     * 524288 + cix] = hn[0];
            out[(size_t)(bbase + 1) * 524288 + cix] = hn[1];
        }

        __syncthreads();
        if (tid == 0) {
            int* fp = &flags[sub];
            int v = s + 1;
            asm volatile("st.release.gpu.b32 [%0], %1;" :: "l"(fp), "r"(v) : "memory");
        }
    }

    // final states: h_final then c_final, each (2, 128, 256)
    const size_t fin = 67108864ull;
    {
        size_t hoff = fin + (size_t)dirq * 32768 + (size_t)bbase * 256 + u0;
        out[hoff]       = hn[0];
        out[hoff + 256] = hn[1];
        size_t coff = hoff + 65536;
        out[coff]       = c[0];
        out[coff + 256] = c[1];
    }
}

extern "C" void kernel_launch(void* const* d_in, const int* in_sizes, int n_in,
                              void* d_out, int out_size) {
    const float* x  = (const float*)d_in[0];
    const float* Wf = (const float*)d_in[1];
    const float* bf = (const float*)d_in[2];
    const float* Wb = (const float*)d_in[3];
    const float* bb = (const float*)d_in[4];
    float* out = (float*)d_out;

    cudaFuncSetAttribute(zx_gemm_kernel, cudaFuncAttributeMaxDynamicSharedMemorySize, 133120);
    cudaFuncSetAttribute(lstm_seq_kernel, cudaFuncAttributeMaxDynamicSharedMemorySize, 122880);

    zero_flags_kernel<<<1, 128>>>();
    dim3 g1(8, 1024, 2);
    zx_gemm_kernel<<<g1, 256, 133120>>>(x, Wf, bf, Wb, bb);
    lstm_seq_kernel<<<128, 256, 122880>>>(Wf, Wb, out);
}